// round 16
// baseline (speedup 1.0000x reference)
#include <cuda_runtime.h>
#include <cuda_fp16.h>
#include <cstdint>

// ---------------------------------------------------------------------------
// LSTM cell, sm_103 base target. R16: BK=128 per stage (8 x K16 per barrier,
// KSTEPS=16) to amortize the per-stage __syncthreads drain over 2x tensor
// work; NSTAGE=2 double buffer (stage 40KB -> 81KB/CTA), 2 CTAs/SM for phase
// decorrelation. CTA 64x96, 128 thr / 4 warps (2Mx2N, Mw32 x 16cols/gate).
// fp16 m16n8k16, f32 acc. Merged f32->half prep.
// ---------------------------------------------------------------------------

static constexpr int BATCH = 16384;
static constexpr int HID   = 1024;
static constexpr int KTOT  = 2048;
static constexpr int BM    = 64;
static constexpr int BN_G  = 32;
static constexpr int GATES = 3;
static constexpr int BK    = 128;          // halfs per stage row (256B)
static constexpr int KSTEPS = KTOT / BK;   // 16
static constexpr int NSTAGE = 2;
static constexpr int NTHR   = 128;

static constexpr uint32_t A_ST  = BM * 256;            // 16 KB
static constexpr uint32_t B_ST  = GATES * BN_G * 256;  // 24 KB
static constexpr uint32_t STAGE = A_ST + B_ST;         // 40 KB
static constexpr uint32_t SMEM_BYTES = NSTAGE * STAGE + 1024;  // ~81 KB

static constexpr long XCHUNKS = (long)BATCH * KTOT / 8;
static constexpr long WCHUNKS = (long)GATES * HID * KTOT / 8;
static constexpr int  PREP_THR = 512;
static constexpr long PREP_BLOCKS = (XCHUNKS + WCHUNKS + PREP_THR - 1) / PREP_THR;

__device__ __half g_X[(long)BATCH * KTOT];
__device__ __half g_W[(long)GATES * HID * KTOT];

__device__ __forceinline__ uint32_t smem_u32(const void* p) {
    uint32_t a;
    asm("{ .reg .u64 t; cvta.to.shared.u64 t, %1; cvt.u32.u64 %0, t; }"
        : "=r"(a) : "l"(p));
    return a;
}

#define CP_ASYNC16(dst, src) \
    asm volatile("cp.async.cg.shared.global [%0], [%1], 16;" :: "r"(dst), "l"(src) : "memory")
#define CP_COMMIT() asm volatile("cp.async.commit_group;" ::: "memory")

#define LDSM4(r, addr)                                                         \
    asm volatile("ldmatrix.sync.aligned.m8n8.x4.shared.b16 {%0,%1,%2,%3}, [%4];" \
        : "=r"((r)[0]), "=r"((r)[1]), "=r"((r)[2]), "=r"((r)[3]) : "r"(addr))

#define MMA_F16(d, a, b0, b1)                                                  \
    asm volatile("mma.sync.aligned.m16n8k16.row.col.f32.f16.f16.f32 "          \
        "{%0,%1,%2,%3},{%4,%5,%6,%7},{%8,%9},{%0,%1,%2,%3};"                   \
        : "+f"((d)[0]), "+f"((d)[1]), "+f"((d)[2]), "+f"((d)[3])               \
        : "r"((a)[0]), "r"((a)[1]), "r"((a)[2]), "r"((a)[3]), "r"(b0), "r"(b1))

__device__ __forceinline__ void cvt_store8(const float4* __restrict__ src,
                                           uint4* __restrict__ dst) {
    const float4 v0 = src[0], v1 = src[1];
    __half2 o[4];
    o[0] = __floats2half2_rn(v0.x, v0.y);
    o[1] = __floats2half2_rn(v0.z, v0.w);
    o[2] = __floats2half2_rn(v1.x, v1.y);
    o[3] = __floats2half2_rn(v1.z, v1.w);
    *dst = *(const uint4*)o;
}

__global__ __launch_bounds__(PREP_THR)
void prep_kernel(const float* __restrict__ x,   const float* __restrict__ h,
                 const float* __restrict__ Wii, const float* __restrict__ Whi,
                 const float* __restrict__ Wif, const float* __restrict__ Whf,
                 const float* __restrict__ Wig, const float* __restrict__ Whg) {
    const long i = (long)blockIdx.x * PREP_THR + threadIdx.x;
    if (i < XCHUNKS) {
        const long row = i >> 8;
        const int  c8  = (int)(i & 255);
        const float4* src = (c8 < 128)
            ? (const float4*)(x + row * 1024 + c8 * 8)
            : (const float4*)(h + row * 1024 + (c8 - 128) * 8);
        cvt_store8(src, (uint4*)g_X + i);
    } else if (i < XCHUNKS + WCHUNKS) {
        const long j = i - XCHUNKS;
        const long grow = j >> 8;
        const int  c8   = (int)(j & 255);
        const int  g    = (int)(grow >> 10);
        const long r    = grow & 1023;
        const float* Wx = (g == 0) ? Wii : (g == 1) ? Wif : Wig;
        const float* Wh = (g == 0) ? Whi : (g == 1) ? Whf : Whg;
        const float4* src = (c8 < 128)
            ? (const float4*)(Wx + r * 1024 + c8 * 8)
            : (const float4*)(Wh + r * 1024 + (c8 - 128) * 8);
        cvt_store8(src, (uint4*)g_W + j);
    }
}

__device__ __forceinline__ float lstm_elem(float gi, float gf, float gg,
                                           float bi, float bf, float bg, float cv) {
    float vi = gi + bi;
    float vf = gf + bf;
    float vg = gg + bg;
    float si = 1.0f / (1.0f + __expf(-vi));
    float sf = 1.0f / (1.0f + __expf(-vf));
    float vgc = fminf(15.0f, fmaxf(-15.0f, vg));
    float e2  = __expf(2.0f * vgc);
    float tg  = (e2 - 1.0f) / (e2 + 1.0f);
    return fmaf(sf, cv, si * tg);
}

// swizzled byte offset within a 256B row: ch = 16B-chunk index 0..15
__device__ __forceinline__ uint32_t sw256(int row, int ch) {
    return (uint32_t)(row * 256 + (((ch & 7) ^ (row & 7)) << 4) + ((ch >> 3) << 7));
}

__global__ __launch_bounds__(NTHR, 2)
void lstm_mma_kernel(const float* __restrict__ c,
                     const float* __restrict__ bii, const float* __restrict__ bhi,
                     const float* __restrict__ bif, const float* __restrict__ bhf,
                     const float* __restrict__ big, const float* __restrict__ bhg,
                     float* __restrict__ out) {
    extern __shared__ char smem_raw[];
    const uint32_t raw   = smem_u32(smem_raw);
    const uint32_t tiles = (raw + 1023u) & ~1023u;
    float* bias = (float*)(smem_raw + (tiles - raw) + NSTAGE * STAGE);

    const int tid  = threadIdx.x;
    const int lane = tid & 31;
    const int wid  = tid >> 5;
    const int wm   = wid >> 1;      // 0..1 : 32-row M tile
    const int wn   = wid & 1;       // 0..1 : 16 cols per gate

    const int m0 = (int)(blockIdx.x >> 5) * BM;       // 256 M-tiles
    const int n0 = (int)(blockIdx.x & 31) * BN_G;     // 32 N-blocks

    if (tid < 96) {
        const int g = tid >> 5, j = tid & 31, n = n0 + j;
        float v;
        if (g == 0)      v = bii[n] + bhi[n];
        else if (g == 1) v = bif[n] + bhf[n];
        else             v = big[n] + bhg[n];
        bias[tid] = v;
    }

    // producer invariants: A 1024 chunks -> 8/thread, B 1536 -> 12/thread ---
    uint32_t aoffs[8]; int aroffm[8];
    #pragma unroll
    for (int i = 0; i < 8; ++i) {
        const int id = tid + i * NTHR;
        const int row = id >> 4, ch = id & 15;
        aoffs[i]  = sw256(row, ch);
        aroffm[i] = row * KTOT + ch * 8;       // relative to g_X + m0*KTOT
    }
    uint32_t boffs[12]; int broff[12];
    #pragma unroll
    for (int i = 0; i < 12; ++i) {
        const int id = tid + i * NTHR;
        const int grow = id >> 4, ch = id & 15;    // grow 0..95
        const int g = grow >> 5, r = grow & 31;
        boffs[i] = sw256(grow, ch) + A_ST;
        broff[i] = (g * HID + n0 + r) * KTOT + ch * 8;
    }
    const __half* gx = g_X + (long)m0 * KTOT;

    // consumer invariants ----------------------------------------------------
    const int a_r  = (lane & 7) + ((lane >> 3) & 1) * 8;
    const int a_kx = lane >> 4;
    const int b_r  = (lane & 7) + ((lane >> 4) << 3);
    const int b_kx = (lane >> 3) & 1;

    uint32_t arow[2], brow[GATES];
    #pragma unroll
    for (int mt = 0; mt < 2; ++mt)
        arow[mt] = (uint32_t)((wm * 32 + mt * 16 + a_r) * 256);
    #pragma unroll
    for (int g = 0; g < GATES; ++g)
        brow[g] = (uint32_t)((g * 32 + wn * 16 + b_r) * 256) + A_ST;

    const uint32_t a_s7 = (uint32_t)(a_r & 7);
    const uint32_t b_s7 = (uint32_t)(b_r & 7);

    float acc[GATES][2][2][4];
    #pragma unroll
    for (int g = 0; g < GATES; ++g)
        #pragma unroll
        for (int mt = 0; mt < 2; ++mt)
            #pragma unroll
            for (int nt = 0; nt < 2; ++nt)
                #pragma unroll
                for (int q = 0; q < 4; ++q) acc[g][mt][nt][q] = 0.0f;

    auto load_stage = [&](int s, int ks) {
        const int kk = ks * BK;
        const uint32_t sb = tiles + (uint32_t)s * STAGE;
        #pragma unroll
        for (int i = 0; i < 8; ++i)
            CP_ASYNC16(sb + aoffs[i], gx + (long)aroffm[i] + kk);
        #pragma unroll
        for (int i = 0; i < 12; ++i)
            CP_ASYNC16(sb + boffs[i], g_W + (long)broff[i] + kk);
    };

    load_stage(0, 0);
    CP_COMMIT();

    for (int ks = 0; ks < KSTEPS; ++ks) {
        asm volatile("cp.async.wait_group 0;" ::: "memory");
        __syncthreads();

        const uint32_t sb = tiles + (uint32_t)(ks & 1) * STAGE;

        #pragma unroll
        for (int kst = 0; kst < 8; ++kst) {            // 8 x K16 per stage
            const int kcA = kst * 2 + a_kx;            // 0..15
            const int kcB = kst * 2 + b_kx;
            const uint32_t aoff = (uint32_t)(((((uint32_t)kcA & 7) ^ a_s7) << 4) + (((uint32_t)kcA >> 3) << 7));
            const uint32_t boff = (uint32_t)(((((uint32_t)kcB & 7) ^ b_s7) << 4) + (((uint32_t)kcB >> 3) << 7));
            uint32_t a[2][4], b[GATES][4];
            #pragma unroll
            for (int mt = 0; mt < 2; ++mt) LDSM4(a[mt], sb + arow[mt] + aoff);
            #pragma unroll
            for (int g = 0; g < GATES; ++g) LDSM4(b[g], sb + brow[g] + boff);
            #pragma unroll
            for (int g = 0; g < GATES; ++g)
                #pragma unroll
                for (int mt = 0; mt < 2; ++mt) {
                    MMA_F16(acc[g][mt][0], a[mt], b[g][0], b[g][1]);
                    MMA_F16(acc[g][mt][1], a[mt], b[g][2], b[g][3]);
                }
        }

        if (ks + 1 < KSTEPS) load_stage((ks + 1) & 1, ks + 1);
        CP_COMMIT();
    }

    // epilogue: register-resident --------------------------------------------
    #pragma unroll
    for (int mt = 0; mt < 2; ++mt) {
        const int mrow = m0 + wm * 32 + mt * 16 + (lane >> 2);
        #pragma unroll
        for (int nt = 0; nt < 2; ++nt) {
            const int nl = wn * 16 + nt * 8 + (lane & 3) * 2;
            const float bi0 = bias[nl],      bi1 = bias[nl + 1];
            const float bf0 = bias[32 + nl], bf1 = bias[32 + nl + 1];
            const float bg0 = bias[64 + nl], bg1 = bias[64 + nl + 1];
            #pragma unroll
            for (int rh = 0; rh < 2; ++rh) {
                const long idx = (long)(mrow + rh * 8) * HID + n0 + nl;
                const float2 cv = *(const float2*)(c + idx);
                float2 ov;
                ov.x = lstm_elem(acc[0][mt][nt][rh * 2],
                                 acc[1][mt][nt][rh * 2],
                                 acc[2][mt][nt][rh * 2], bi0, bf0, bg0, cv.x);
                ov.y = lstm_elem(acc[0][mt][nt][rh * 2 + 1],
                                 acc[1][mt][nt][rh * 2 + 1],
                                 acc[2][mt][nt][rh * 2 + 1], bi1, bf1, bg1, cv.y);
                *(float2*)(out + idx) = ov;
            }
        }
    }
}

extern "C" void kernel_launch(void* const* d_in, const int* in_sizes, int n_in,
                              void* d_out, int out_size) {
    const float* x   = (const float*)d_in[0];
    const float* h   = (const float*)d_in[1];
    const float* c   = (const float*)d_in[2];
    const float* Wii = (const float*)d_in[3];
    const float* bii = (const float*)d_in[4];
    const float* Whi = (const float*)d_in[5];
    const float* bhi = (const float*)d_in[6];
    const float* Wif = (const float*)d_in[7];
    const float* bif = (const float*)d_in[8];
    const float* Whf = (const float*)d_in[9];
    const float* bhf = (const float*)d_in[10];
    const float* Wig = (const float*)d_in[11];
    const float* big = (const float*)d_in[12];
    const float* Whg = (const float*)d_in[13];
    const float* bhg = (const float*)d_in[14];
    float* out = (float*)d_out;

    cudaFuncSetAttribute(lstm_mma_kernel,
                         cudaFuncAttributeMaxDynamicSharedMemorySize, SMEM_BYTES);

    prep_kernel<<<(int)PREP_BLOCKS, PREP_THR>>>(x, h, Wii, Whi, Wif, Whf, Wig, Whg);

    dim3 grid((BATCH / BM) * (HID / BN_G));   // 8192
    lstm_mma_kernel<<<grid, NTHR, SMEM_BYTES>>>(
        c, bii, bhi, bif, bhf, big, bhg, out);
}

// round 17
// speedup vs baseline: 1.4320x; 1.4320x over previous
#include <cuda_runtime.h>
#include <cuda_fp16.h>
#include <cstdint>

// ---------------------------------------------------------------------------
// LSTM cell, sm_103 base target. R17: crossbar-balanced geometry. Model:
// crossbar allows ~230B smem traffic per MMA at full tensor rate; R15 spent
// 320 (cap 72%). CTA 96x96, 4 warps (Mw48 x Nf48) -> 250B/MMA (cap 92%),
// stage 24KB, NSTAGE=3 -> 74KB/CTA -> 3 CTAs/SM (phase decorrelation).
// M=16384 not divisible by 96: A-row clamp + guarded epilogue.
// fp16 m16n8k16, f32 acc. Merged f32->half prep.
// ---------------------------------------------------------------------------

static constexpr int BATCH = 16384;
static constexpr int HID   = 1024;
static constexpr int KTOT  = 2048;
static constexpr int BM    = 96;
static constexpr int BN_G  = 32;
static constexpr int GATES = 3;
static constexpr int BK    = 64;           // halfs per stage row (128B)
static constexpr int KSTEPS = KTOT / BK;   // 32
static constexpr int NSTAGE = 3;
static constexpr int NTHR   = 128;
static constexpr int MTILES = (BATCH + BM - 1) / BM;   // 171

static constexpr uint32_t A_ST  = BM * 128;            // 12 KB
static constexpr uint32_t B_ST  = GATES * BN_G * 128;  // 12 KB
static constexpr uint32_t STAGE = A_ST + B_ST;         // 24 KB
static constexpr uint32_t SMEM_BYTES = NSTAGE * STAGE + 1024;  // ~73.8 KB

static constexpr long XCHUNKS = (long)BATCH * KTOT / 8;
static constexpr long WCHUNKS = (long)GATES * HID * KTOT / 8;
static constexpr int  PREP_THR = 512;
static constexpr long PREP_BLOCKS = (XCHUNKS + WCHUNKS + PREP_THR - 1) / PREP_THR;

__device__ __half g_X[(long)BATCH * KTOT];
__device__ __half g_W[(long)GATES * HID * KTOT];

__device__ __forceinline__ uint32_t smem_u32(const void* p) {
    uint32_t a;
    asm("{ .reg .u64 t; cvta.to.shared.u64 t, %1; cvt.u32.u64 %0, t; }"
        : "=r"(a) : "l"(p));
    return a;
}

#define CP_ASYNC16(dst, src) \
    asm volatile("cp.async.cg.shared.global [%0], [%1], 16;" :: "r"(dst), "l"(src) : "memory")
#define CP_COMMIT() asm volatile("cp.async.commit_group;" ::: "memory")

#define LDSM4(r, addr)                                                         \
    asm volatile("ldmatrix.sync.aligned.m8n8.x4.shared.b16 {%0,%1,%2,%3}, [%4];" \
        : "=r"((r)[0]), "=r"((r)[1]), "=r"((r)[2]), "=r"((r)[3]) : "r"(addr))

#define MMA_F16(d, a, b0, b1)                                                  \
    asm volatile("mma.sync.aligned.m16n8k16.row.col.f32.f16.f16.f32 "          \
        "{%0,%1,%2,%3},{%4,%5,%6,%7},{%8,%9},{%0,%1,%2,%3};"                   \
        : "+f"((d)[0]), "+f"((d)[1]), "+f"((d)[2]), "+f"((d)[3])               \
        : "r"((a)[0]), "r"((a)[1]), "r"((a)[2]), "r"((a)[3]), "r"(b0), "r"(b1))

__device__ __forceinline__ void cvt_store8(const float4* __restrict__ src,
                                           uint4* __restrict__ dst) {
    const float4 v0 = src[0], v1 = src[1];
    __half2 o[4];
    o[0] = __floats2half2_rn(v0.x, v0.y);
    o[1] = __floats2half2_rn(v0.z, v0.w);
    o[2] = __floats2half2_rn(v1.x, v1.y);
    o[3] = __floats2half2_rn(v1.z, v1.w);
    *dst = *(const uint4*)o;
}

__global__ __launch_bounds__(PREP_THR)
void prep_kernel(const float* __restrict__ x,   const float* __restrict__ h,
                 const float* __restrict__ Wii, const float* __restrict__ Whi,
                 const float* __restrict__ Wif, const float* __restrict__ Whf,
                 const float* __restrict__ Wig, const float* __restrict__ Whg) {
    const long i = (long)blockIdx.x * PREP_THR + threadIdx.x;
    if (i < XCHUNKS) {
        const long row = i >> 8;
        const int  c8  = (int)(i & 255);
        const float4* src = (c8 < 128)
            ? (const float4*)(x + row * 1024 + c8 * 8)
            : (const float4*)(h + row * 1024 + (c8 - 128) * 8);
        cvt_store8(src, (uint4*)g_X + i);
    } else if (i < XCHUNKS + WCHUNKS) {
        const long j = i - XCHUNKS;
        const long grow = j >> 8;
        const int  c8   = (int)(j & 255);
        const int  g    = (int)(grow >> 10);
        const long r    = grow & 1023;
        const float* Wx = (g == 0) ? Wii : (g == 1) ? Wif : Wig;
        const float* Wh = (g == 0) ? Whi : (g == 1) ? Whf : Whg;
        const float4* src = (c8 < 128)
            ? (const float4*)(Wx + r * 1024 + c8 * 8)
            : (const float4*)(Wh + r * 1024 + (c8 - 128) * 8);
        cvt_store8(src, (uint4*)g_W + j);
    }
}

__device__ __forceinline__ float lstm_elem(float gi, float gf, float gg,
                                           float bi, float bf, float bg, float cv) {
    float vi = gi + bi;
    float vf = gf + bf;
    float vg = gg + bg;
    float si = 1.0f / (1.0f + __expf(-vi));
    float sf = 1.0f / (1.0f + __expf(-vf));
    float vgc = fminf(15.0f, fmaxf(-15.0f, vg));
    float e2  = __expf(2.0f * vgc);
    float tg  = (e2 - 1.0f) / (e2 + 1.0f);
    return fmaf(sf, cv, si * tg);
}

__global__ __launch_bounds__(NTHR, 3)
void lstm_mma_kernel(const float* __restrict__ c,
                     const float* __restrict__ bii, const float* __restrict__ bhi,
                     const float* __restrict__ bif, const float* __restrict__ bhf,
                     const float* __restrict__ big, const float* __restrict__ bhg,
                     float* __restrict__ out) {
    extern __shared__ char smem_raw[];
    const uint32_t raw   = smem_u32(smem_raw);
    const uint32_t tiles = (raw + 1023u) & ~1023u;
    float* bias = (float*)(smem_raw + (tiles - raw) + NSTAGE * STAGE);

    const int tid  = threadIdx.x;
    const int lane = tid & 31;
    const int wid  = tid >> 5;
    const int wm   = wid >> 1;      // 0..1 : 48-row M tile
    const int wn   = wid & 1;       // 0..1 : 16 cols per gate

    const int m0 = (int)(blockIdx.x >> 5) * BM;       // 171 M-tiles (last partial)
    const int n0 = (int)(blockIdx.x & 31) * BN_G;     // 32 N-blocks

    if (tid < 96) {
        const int g = tid >> 5, j = tid & 31, n = n0 + j;
        float v;
        if (g == 0)      v = bii[n] + bhi[n];
        else if (g == 1) v = bif[n] + bhf[n];
        else             v = big[n] + bhg[n];
        bias[tid] = v;
    }

    // producer invariants: A 768 chunks -> 6/thread (row clamped), B 768 -> 6
    uint32_t aoffs[6]; const __half* asrc[6];
    #pragma unroll
    for (int i = 0; i < 6; ++i) {
        const int id = tid + i * NTHR;
        const int row = id >> 3, ch = id & 7;
        aoffs[i] = (uint32_t)(row * 128 + ((ch ^ (row & 7)) << 4));
        int gr = m0 + row; if (gr > BATCH - 1) gr = BATCH - 1;   // clamp
        asrc[i]  = g_X + (long)gr * KTOT + ch * 8;
    }
    uint32_t boffs[6]; int broff[6];
    #pragma unroll
    for (int i = 0; i < 6; ++i) {
        const int id = tid + i * NTHR;
        const int grow = id >> 3, ch = id & 7;     // grow 0..95
        const int g = grow >> 5, r = grow & 31;
        boffs[i] = (uint32_t)(grow * 128 + ((ch ^ (r & 7)) << 4)) + A_ST;
        broff[i] = (g * HID + n0 + r) * KTOT + ch * 8;
    }

    // consumer invariants ----------------------------------------------------
    const int a_r  = (lane & 7) + ((lane >> 3) & 1) * 8;
    const int a_kx = lane >> 4;
    const int b_r  = (lane & 7) + ((lane >> 4) << 3);
    const int b_kx = (lane >> 3) & 1;

    uint32_t arow[3], brow[GATES];
    #pragma unroll
    for (int mt = 0; mt < 3; ++mt)
        arow[mt] = (uint32_t)((wm * 48 + mt * 16 + a_r) * 128);
    #pragma unroll
    for (int g = 0; g < GATES; ++g)
        brow[g] = (uint32_t)((g * 32 + wn * 16 + b_r) * 128) + A_ST;

    const uint32_t a_s7 = (uint32_t)(a_r & 7);
    const uint32_t b_s7 = (uint32_t)(b_r & 7);

    float acc[GATES][3][2][4];
    #pragma unroll
    for (int g = 0; g < GATES; ++g)
        #pragma unroll
        for (int mt = 0; mt < 3; ++mt)
            #pragma unroll
            for (int nt = 0; nt < 2; ++nt)
                #pragma unroll
                for (int q = 0; q < 4; ++q) acc[g][mt][nt][q] = 0.0f;

    auto load_stage = [&](int s, int ks) {
        const int kk = ks * BK;
        const uint32_t sb = tiles + (uint32_t)s * STAGE;
        #pragma unroll
        for (int i = 0; i < 6; ++i)
            CP_ASYNC16(sb + aoffs[i], asrc[i] + kk);
        #pragma unroll
        for (int i = 0; i < 6; ++i)
            CP_ASYNC16(sb + boffs[i], g_W + (long)broff[i] + kk);
    };

    #pragma unroll
    for (int s = 0; s < NSTAGE - 1; ++s) { load_stage(s, s); CP_COMMIT(); }

    int sidx = 0;
    int pidx = NSTAGE - 1;
    for (int ks = 0; ks < KSTEPS; ++ks) {
        asm volatile("cp.async.wait_group %0;" :: "n"(NSTAGE - 2));
        __syncthreads();

        const uint32_t sb = tiles + (uint32_t)sidx * STAGE;

        #pragma unroll
        for (int kst = 0; kst < 4; ++kst) {
            const uint32_t aoff = (uint32_t)(((kst * 2 + a_kx) ^ a_s7) << 4);
            const uint32_t boff = (uint32_t)(((kst * 2 + b_kx) ^ b_s7) << 4);
            uint32_t a[3][4], b[GATES][4];
            #pragma unroll
            for (int mt = 0; mt < 3; ++mt) LDSM4(a[mt], sb + arow[mt] + aoff);
            #pragma unroll
            for (int g = 0; g < GATES; ++g) LDSM4(b[g], sb + brow[g] + boff);
            #pragma unroll
            for (int g = 0; g < GATES; ++g)
                #pragma unroll
                for (int mt = 0; mt < 3; ++mt) {
                    MMA_F16(acc[g][mt][0], a[mt], b[g][0], b[g][1]);
                    MMA_F16(acc[g][mt][1], a[mt], b[g][2], b[g][3]);
                }
        }

        const int pf = ks + NSTAGE - 1;
        if (pf < KSTEPS) load_stage(pidx, pf);
        CP_COMMIT();
        if (++sidx == NSTAGE) sidx = 0;
        if (++pidx == NSTAGE) pidx = 0;
    }

    // epilogue: register-resident, guarded for the partial last M-tile -------
    #pragma unroll
    for (int mt = 0; mt < 3; ++mt) {
        const int mrow = m0 + wm * 48 + mt * 16 + (lane >> 2);
        #pragma unroll
        for (int nt = 0; nt < 2; ++nt) {
            const int nl = wn * 16 + nt * 8 + (lane & 3) * 2;
            const float bi0 = bias[nl],      bi1 = bias[nl + 1];
            const float bf0 = bias[32 + nl], bf1 = bias[32 + nl + 1];
            const float bg0 = bias[64 + nl], bg1 = bias[64 + nl + 1];
            #pragma unroll
            for (int rh = 0; rh < 2; ++rh) {
                const int r = mrow + rh * 8;
                if (r < BATCH) {
                    const long idx = (long)r * HID + n0 + nl;
                    const float2 cv = *(const float2*)(c + idx);
                    float2 ov;
                    ov.x = lstm_elem(acc[0][mt][nt][rh * 2],
                                     acc[1][mt][nt][rh * 2],
                                     acc[2][mt][nt][rh * 2], bi0, bf0, bg0, cv.x);
                    ov.y = lstm_elem(acc[0][mt][nt][rh * 2 + 1],
                                     acc[1][mt][nt][rh * 2 + 1],
                                     acc[2][mt][nt][rh * 2 + 1], bi1, bf1, bg1, cv.y);
                    *(float2*)(out + idx) = ov;
                }
            }
        }
    }
}

extern "C" void kernel_launch(void* const* d_in, const int* in_sizes, int n_in,
                              void* d_out, int out_size) {
    const float* x   = (const float*)d_in[0];
    const float* h   = (const float*)d_in[1];
    const float* c   = (const float*)d_in[2];
    const float* Wii = (const float*)d_in[3];
    const float* bii = (const float*)d_in[4];
    const float* Whi = (const float*)d_in[5];
    const float* bhi = (const float*)d_in[6];
    const float* Wif = (const float*)d_in[7];
    const float* bif = (const float*)d_in[8];
    const float* Whf = (const float*)d_in[9];
    const float* bhf = (const float*)d_in[10];
    const float* Wig = (const float*)d_in[11];
    const float* big = (const float*)d_in[12];
    const float* Whg = (const float*)d_in[13];
    const float* bhg = (const float*)d_in[14];
    float* out = (float*)d_out;

    cudaFuncSetAttribute(lstm_mma_kernel,
                         cudaFuncAttributeMaxDynamicSharedMemorySize, SMEM_BYTES);

    prep_kernel<<<(int)PREP_BLOCKS, PREP_THR>>>(x, h, Wii, Whi, Wif, Whf, Wig, Whg);

    dim3 grid(MTILES * (HID / BN_G));   // 171 * 32 = 5472
    lstm_mma_kernel<<<grid, NTHR, SMEM_BYTES>>>(
        c, bii, bhi, bif, bhf, big, bhg, out);
}